// round 1
// baseline (speedup 1.0000x reference)
#include <cuda_runtime.h>
#include <math.h>

#define BB 4096
#define EE 128
#define MMOD 8
#define NSTEPS 3
#define HDIM 256
#define CDIM 16
#define RT 32                 // rows per tile
#define NTHREADS 256
#define MAX_TILES (BB/RT + MMOD)   // 136

// Scratch (static __device__ — no allocation allowed)
__device__ float g_X[BB * EE];                    // recurrent state, 2 MB
__device__ int   g_order[NSTEPS * BB];            // per-step rows sorted by module
__device__ int   g_tiles[NSTEPS * MAX_TILES * 3]; // (module, base, cnt) per tile

// ---------------------------------------------------------------------------
// Setup: per-step counting sort of rows by module + tile metadata
// ---------------------------------------------------------------------------
__global__ void setup_kernel(const int* __restrict__ module_ids) {
    __shared__ int cnt[MMOD], cur[MMOD];
    int tid = threadIdx.x;
    for (int s = 0; s < NSTEPS; s++) {
        if (tid < MMOD) cnt[tid] = 0;
        __syncthreads();
        for (int b = tid; b < BB; b += NTHREADS)
            atomicAdd(&cnt[module_ids[b * NSTEPS + s]], 1);
        __syncthreads();
        if (tid == 0) {
            int o = 0, t = 0;
            for (int m = 0; m < MMOD; m++) {
                cur[m] = o;
                int c = cnt[m];
                for (int chunk = 0; chunk < c; chunk += RT) {
                    g_tiles[(s * MAX_TILES + t) * 3 + 0] = m;
                    g_tiles[(s * MAX_TILES + t) * 3 + 1] = o + chunk;
                    g_tiles[(s * MAX_TILES + t) * 3 + 2] = min(RT, c - chunk);
                    t++;
                }
                o += c;
            }
            for (; t < MAX_TILES; t++)
                g_tiles[(s * MAX_TILES + t) * 3 + 2] = 0;
        }
        __syncthreads();
        for (int b = tid; b < BB; b += NTHREADS) {
            int m = module_ids[b * NSTEPS + s];
            int p = atomicAdd(&cur[m], 1);
            g_order[s * BB + p] = b;
        }
        __syncthreads();
    }
}

// ---------------------------------------------------------------------------
// Gather initial state x0 = embedding[entity_ids[:,0]]
// ---------------------------------------------------------------------------
__global__ void gather_x0(const int* __restrict__ entity_ids,
                          const float* __restrict__ emb) {
    int i = blockIdx.x * blockDim.x + threadIdx.x;  // over BB*EE
    int b = i >> 7, e = i & (EE - 1);
    g_X[i] = emb[(size_t)entity_ids[b * (NSTEPS + 1)] * EE + e];
}

// ---------------------------------------------------------------------------
// One recurrent step for one (module, row-tile):
//   h_in = relu(X @ W_in[m] + b_in[m]); h_bi = relu(Bias @ W_bias[m] + b_bias[m])
//   X'   = tanh([h_in, h_bi] @ W_f[m] + b_f[m])
// 256 threads: o = tid&127 output column, half = tid>>7 handles 16 rows.
// ---------------------------------------------------------------------------
__global__ void step_kernel(int s,
                            const float* __restrict__ emb,
                            const int* __restrict__ entity_ids,
                            const float* __restrict__ W_in,  const float* __restrict__ b_in,
                            const float* __restrict__ W_bias,const float* __restrict__ b_bias,
                            const float* __restrict__ W_f,   const float* __restrict__ b_f) {
    __shared__ float S[RT][2 * EE];   // 32 x 256 f32 = 32 KB (X|Bias, then reused as H)
    __shared__ int ridx[RT];
    __shared__ int eidn[RT];
    __shared__ int s_m, s_base, s_cnt;

    int tid = threadIdx.x;
    if (tid == 0) {
        int t = blockIdx.x;
        s_m    = g_tiles[(s * MAX_TILES + t) * 3 + 0];
        s_base = g_tiles[(s * MAX_TILES + t) * 3 + 1];
        s_cnt  = g_tiles[(s * MAX_TILES + t) * 3 + 2];
    }
    __syncthreads();
    const int cnt = s_cnt;
    if (cnt == 0) return;
    const int m = s_m, base = s_base;

    if (tid < RT) {
        int row = g_order[s * BB + base + ((tid < cnt) ? tid : 0)];
        ridx[tid] = row;
        eidn[tid] = entity_ids[row * (NSTEPS + 1) + s + 1];
    }
    __syncthreads();

    // Load X tile and Bias tile (gather) into SMEM
    for (int i = tid; i < RT * EE; i += NTHREADS) {
        int r = i >> 7, e = i & (EE - 1);
        S[r][e]      = g_X[ridx[r] * EE + e];
        S[r][EE + e] = emb[(size_t)eidn[r] * EE + e];
    }
    __syncthreads();

    const int o    = tid & (EE - 1);
    const int half = tid >> 7;
    const int r0   = half * (RT / 2);

    float acc_in[RT / 2], acc_bi[RT / 2];
#pragma unroll
    for (int r = 0; r < RT / 2; r++) { acc_in[r] = 0.f; acc_bi[r] = 0.f; }

    const float* Wi = W_in   + m * EE * EE;
    const float* Wb = W_bias + m * EE * EE;
#pragma unroll 4
    for (int e = 0; e < EE; e += 4) {
        float w0 = Wi[(e + 0) * EE + o], w1 = Wi[(e + 1) * EE + o];
        float w2 = Wi[(e + 2) * EE + o], w3 = Wi[(e + 3) * EE + o];
        float v0 = Wb[(e + 0) * EE + o], v1 = Wb[(e + 1) * EE + o];
        float v2 = Wb[(e + 2) * EE + o], v3 = Wb[(e + 3) * EE + o];
#pragma unroll
        for (int r = 0; r < RT / 2; r++) {
            float4 x4 = *(const float4*)&S[r0 + r][e];
            acc_in[r] = fmaf(x4.x, w0, acc_in[r]);
            acc_in[r] = fmaf(x4.y, w1, acc_in[r]);
            acc_in[r] = fmaf(x4.z, w2, acc_in[r]);
            acc_in[r] = fmaf(x4.w, w3, acc_in[r]);
            float4 y4 = *(const float4*)&S[r0 + r][EE + e];
            acc_bi[r] = fmaf(y4.x, v0, acc_bi[r]);
            acc_bi[r] = fmaf(y4.y, v1, acc_bi[r]);
            acc_bi[r] = fmaf(y4.z, v2, acc_bi[r]);
            acc_bi[r] = fmaf(y4.w, v3, acc_bi[r]);
        }
    }

    const float bi = b_in[m * EE + o];
    const float bb = b_bias[m * EE + o];
    __syncthreads();   // all reads of S done before overwrite as H
#pragma unroll
    for (int r = 0; r < RT / 2; r++) {
        S[r0 + r][o]      = fmaxf(acc_in[r] + bi, 0.f);
        S[r0 + r][EE + o] = fmaxf(acc_bi[r] + bb, 0.f);
    }
    __syncthreads();

    float acc[RT / 2];
#pragma unroll
    for (int r = 0; r < RT / 2; r++) acc[r] = 0.f;
    const float* Wf = W_f + m * 2 * EE * EE;
#pragma unroll 4
    for (int f = 0; f < 2 * EE; f += 4) {
        float w0 = Wf[(f + 0) * EE + o], w1 = Wf[(f + 1) * EE + o];
        float w2 = Wf[(f + 2) * EE + o], w3 = Wf[(f + 3) * EE + o];
#pragma unroll
        for (int r = 0; r < RT / 2; r++) {
            float4 h4 = *(const float4*)&S[r0 + r][f];
            acc[r] = fmaf(h4.x, w0, acc[r]);
            acc[r] = fmaf(h4.y, w1, acc[r]);
            acc[r] = fmaf(h4.z, w2, acc[r]);
            acc[r] = fmaf(h4.w, w3, acc[r]);
        }
    }
    const float bf = b_f[m * EE + o];
#pragma unroll
    for (int r = 0; r < RT / 2; r++) {
        if (r0 + r < cnt)
            g_X[ridx[r0 + r] * EE + o] = tanhf(acc[r] + bf);
    }
}

// ---------------------------------------------------------------------------
// Head: out = relu(X @ W1 + b1) @ W2 + b2
// ---------------------------------------------------------------------------
__global__ void head_kernel(const float* __restrict__ W1, const float* __restrict__ b1,
                            const float* __restrict__ W2, const float* __restrict__ b2,
                            float* __restrict__ out) {
    __shared__ float S[RT][HDIM];   // 32 KB; cols 0..127 first hold X, then full H
    int tid  = threadIdx.x;
    int row0 = blockIdx.x * RT;

    for (int i = tid; i < RT * EE; i += NTHREADS) {
        int r = i >> 7, e = i & (EE - 1);
        S[r][e] = g_X[(row0 + r) * EE + e];
    }
    __syncthreads();

    const int oh = tid;  // 0..255 hidden column
    float acc[RT];
#pragma unroll
    for (int r = 0; r < RT; r++) acc[r] = 0.f;
#pragma unroll 4
    for (int e = 0; e < EE; e += 4) {
        float w0 = W1[(e + 0) * HDIM + oh], w1 = W1[(e + 1) * HDIM + oh];
        float w2 = W1[(e + 2) * HDIM + oh], w3 = W1[(e + 3) * HDIM + oh];
#pragma unroll
        for (int r = 0; r < RT; r++) {
            float4 x4 = *(const float4*)&S[r][e];
            acc[r] = fmaf(x4.x, w0, acc[r]);
            acc[r] = fmaf(x4.y, w1, acc[r]);
            acc[r] = fmaf(x4.z, w2, acc[r]);
            acc[r] = fmaf(x4.w, w3, acc[r]);
        }
    }
    const float bh = b1[oh];
    __syncthreads();
#pragma unroll
    for (int r = 0; r < RT; r++) S[r][oh] = fmaxf(acc[r] + bh, 0.f);
    __syncthreads();

    const int c  = tid & (CDIM - 1);
    const int rr = tid >> 4;           // 0..15
#pragma unroll
    for (int p = 0; p < 2; p++) {
        int r = p * 16 + rr;
        float sum = b2[c];
#pragma unroll 4
        for (int h = 0; h < HDIM; h += 4) {
            float4 h4 = *(const float4*)&S[r][h];
            sum = fmaf(h4.x, W2[(h + 0) * CDIM + c], sum);
            sum = fmaf(h4.y, W2[(h + 1) * CDIM + c], sum);
            sum = fmaf(h4.z, W2[(h + 2) * CDIM + c], sum);
            sum = fmaf(h4.w, W2[(h + 3) * CDIM + c], sum);
        }
        out[(row0 + r) * CDIM + c] = sum;
    }
}

// ---------------------------------------------------------------------------
extern "C" void kernel_launch(void* const* d_in, const int* in_sizes, int n_in,
                              void* d_out, int out_size) {
    const int*   entity_ids = (const int*)d_in[0];
    const int*   module_ids = (const int*)d_in[1];
    const float* emb        = (const float*)d_in[2];
    const float* W_in       = (const float*)d_in[3];
    const float* b_in       = (const float*)d_in[4];
    const float* W_bias     = (const float*)d_in[5];
    const float* b_bias     = (const float*)d_in[6];
    const float* W_f        = (const float*)d_in[7];
    const float* b_f        = (const float*)d_in[8];
    const float* W1         = (const float*)d_in[9];
    const float* b1         = (const float*)d_in[10];
    const float* W2         = (const float*)d_in[11];
    const float* b2         = (const float*)d_in[12];
    float* out = (float*)d_out;

    setup_kernel<<<1, NTHREADS>>>(module_ids);
    gather_x0<<<(BB * EE) / NTHREADS, NTHREADS>>>(entity_ids, emb);
    for (int s = 0; s < NSTEPS; s++)
        step_kernel<<<MAX_TILES, NTHREADS>>>(s, emb, entity_ids,
                                             W_in, b_in, W_bias, b_bias, W_f, b_f);
    head_kernel<<<BB / RT, NTHREADS>>>(W1, b1, W2, b2, out);
}

// round 2
// speedup vs baseline: 1.1418x; 1.1418x over previous
#include <cuda_runtime.h>
#include <math.h>

#define BB 4096
#define EE 128
#define MMOD 8
#define NSTEPS 3
#define HDIM 256
#define CDIM 16
#define RT 32                 // rows per tile
#define NPAIR (RT/2)          // 16 row-pairs
#define STHREADS 512
#define MAX_TILES (BB/RT + MMOD)   // 136

typedef unsigned long long ull;

// Scratch (static __device__ — no allocation allowed)
__device__ float g_X[BB * EE];                    // recurrent state, 2 MB
__device__ int   g_order[NSTEPS * BB];            // per-step rows sorted by module
__device__ int   g_tiles[NSTEPS * MAX_TILES * 3]; // (module, base, cnt) per tile

// ---------------- f32x2 helpers (FFMA2 path, sm_103a) ----------------------
__device__ __forceinline__ ull bcast2(float v) {
    ull r; asm("mov.b64 %0, {%1, %1};" : "=l"(r) : "f"(v)); return r;
}
__device__ __forceinline__ ull fma2(ull a, ull b, ull c) {
    ull d; asm("fma.rn.f32x2 %0, %1, %2, %3;" : "=l"(d) : "l"(a), "l"(b), "l"(c));
    return d;
}
__device__ __forceinline__ float2 unpack2(ull v) {
    float2 f; asm("mov.b64 {%0, %1}, %2;" : "=f"(f.x), "=f"(f.y) : "l"(v)); return f;
}

// ---------------------------------------------------------------------------
// Setup: per-step counting sort of rows by module + tile metadata
// ---------------------------------------------------------------------------
__global__ void setup_kernel(const int* __restrict__ module_ids) {
    __shared__ int cnt[MMOD], cur[MMOD];
    int tid = threadIdx.x;
    for (int s = 0; s < NSTEPS; s++) {
        if (tid < MMOD) cnt[tid] = 0;
        __syncthreads();
        for (int b = tid; b < BB; b += 256)
            atomicAdd(&cnt[module_ids[b * NSTEPS + s]], 1);
        __syncthreads();
        if (tid == 0) {
            int o = 0, t = 0;
            for (int m = 0; m < MMOD; m++) {
                cur[m] = o;
                int c = cnt[m];
                for (int chunk = 0; chunk < c; chunk += RT) {
                    g_tiles[(s * MAX_TILES + t) * 3 + 0] = m;
                    g_tiles[(s * MAX_TILES + t) * 3 + 1] = o + chunk;
                    g_tiles[(s * MAX_TILES + t) * 3 + 2] = min(RT, c - chunk);
                    t++;
                }
                o += c;
            }
            for (; t < MAX_TILES; t++)
                g_tiles[(s * MAX_TILES + t) * 3 + 2] = 0;
        }
        __syncthreads();
        for (int b = tid; b < BB; b += 256) {
            int m = module_ids[b * NSTEPS + s];
            int p = atomicAdd(&cur[m], 1);
            g_order[s * BB + p] = b;
        }
        __syncthreads();
    }
}

// ---------------------------------------------------------------------------
// Gather initial state x0 = embedding[entity_ids[:,0]]
// ---------------------------------------------------------------------------
__global__ void gather_x0(const int* __restrict__ entity_ids,
                          const float* __restrict__ emb) {
    int i = blockIdx.x * blockDim.x + threadIdx.x;  // over BB*EE
    int b = i >> 7, e = i & (EE - 1);
    g_X[i] = emb[(size_t)entity_ids[b * (NSTEPS + 1)] * EE + e];
}

// ---------------------------------------------------------------------------
// One recurrent step for one (module, row-tile). Row-PAIR packed f32x2 math.
// SMEM layout (float2 SH[16*256], 32KB), phase 1: X(p,e)=SH[p*128+e],
// B(p,e)=SH[2048+p*128+e]; phase 2 (after sync): H(p,f)=SH[p*256+f].
// 512 threads: o = tid&127 (output col), g = tid>>7 (0..3) -> pairs 4g..4g+3.
// ---------------------------------------------------------------------------
__global__ __launch_bounds__(STHREADS, 1)
void step_kernel(int s,
                 const float* __restrict__ emb,
                 const int* __restrict__ entity_ids,
                 const float* __restrict__ W_in,  const float* __restrict__ b_in,
                 const float* __restrict__ W_bias,const float* __restrict__ b_bias,
                 const float* __restrict__ W_f,   const float* __restrict__ b_f) {
    __shared__ __align__(16) float2 SH[NPAIR * 2 * EE];   // 32 KB
    __shared__ int ridx[RT];
    __shared__ int s_m, s_base, s_cnt;

    int tid = threadIdx.x;
    if (tid == 0) {
        int t = blockIdx.x;
        s_m    = g_tiles[(s * MAX_TILES + t) * 3 + 0];
        s_base = g_tiles[(s * MAX_TILES + t) * 3 + 1];
        s_cnt  = g_tiles[(s * MAX_TILES + t) * 3 + 2];
    }
    __syncthreads();
    const int cnt = s_cnt;
    if (cnt == 0) return;
    const int m = s_m, base = s_base;

    __shared__ int eidn[RT];
    if (tid < RT) {
        int row = g_order[s * BB + base + ((tid < cnt) ? tid : 0)];
        ridx[tid] = row;
        eidn[tid] = entity_ids[row * (NSTEPS + 1) + s + 1];
    }
    __syncthreads();

    // Load X tile and Bias tile (gather) into pair-interleaved SMEM
    float* SHf = (float*)SH;
    for (int i = tid; i < RT * EE; i += STHREADS) {
        int r = i >> 7, e = i & (EE - 1);
        int p = r >> 1, comp = r & 1;
        SHf[p * 256 + 2 * e + comp]              = g_X[ridx[r] * EE + e];
        SHf[2 * 2048 + p * 256 + 2 * e + comp]   = emb[(size_t)eidn[r] * EE + e];
    }
    __syncthreads();

    const int o = tid & (EE - 1);
    const int g = tid >> 7;          // 0..3
    const int p0 = g * 4;

    ull accI[4], accB[4];
#pragma unroll
    for (int p = 0; p < 4; p++) { accI[p] = 0ull; accB[p] = 0ull; }

    const float* Wi = W_in   + m * EE * EE;
    const float* Wb = W_bias + m * EE * EE;
#pragma unroll 2
    for (int e = 0; e < EE; e += 2) {
        ull wi0 = bcast2(Wi[(e + 0) * EE + o]);
        ull wi1 = bcast2(Wi[(e + 1) * EE + o]);
        ull wb0 = bcast2(Wb[(e + 0) * EE + o]);
        ull wb1 = bcast2(Wb[(e + 1) * EE + o]);
#pragma unroll
        for (int p = 0; p < 4; p++) {
            int pp = p0 + p;
            ulonglong2 x2 = *(const ulonglong2*)&SH[pp * EE + e];
            accI[p] = fma2(x2.x, wi0, accI[p]);
            accI[p] = fma2(x2.y, wi1, accI[p]);
            ulonglong2 b2 = *(const ulonglong2*)&SH[2048 + pp * EE + e];
            accB[p] = fma2(b2.x, wb0, accB[p]);
            accB[p] = fma2(b2.y, wb1, accB[p]);
        }
    }

    const float bi = b_in[m * EE + o];
    const float bb = b_bias[m * EE + o];
    __syncthreads();   // all reads of X/B done before overwrite as H
#pragma unroll
    for (int p = 0; p < 4; p++) {
        int pp = p0 + p;
        float2 vI = unpack2(accI[p]);
        float2 vB = unpack2(accB[p]);
        SH[pp * 256 + o]      = make_float2(fmaxf(vI.x + bi, 0.f), fmaxf(vI.y + bi, 0.f));
        SH[pp * 256 + EE + o] = make_float2(fmaxf(vB.x + bb, 0.f), fmaxf(vB.y + bb, 0.f));
    }
    __syncthreads();

    ull accF[4];
#pragma unroll
    for (int p = 0; p < 4; p++) accF[p] = 0ull;
    const float* Wf = W_f + m * 2 * EE * EE;
#pragma unroll 2
    for (int f = 0; f < 2 * EE; f += 2) {
        ull w0 = bcast2(Wf[(f + 0) * EE + o]);
        ull w1 = bcast2(Wf[(f + 1) * EE + o]);
#pragma unroll
        for (int p = 0; p < 4; p++) {
            int pp = p0 + p;
            ulonglong2 h2 = *(const ulonglong2*)&SH[pp * 256 + f];
            accF[p] = fma2(h2.x, w0, accF[p]);
            accF[p] = fma2(h2.y, w1, accF[p]);
        }
    }
    const float bf = b_f[m * EE + o];
#pragma unroll
    for (int p = 0; p < 4; p++) {
        int pp = p0 + p;
        float2 v = unpack2(accF[p]);
        int ra = 2 * pp, rb = 2 * pp + 1;
        if (ra < cnt) g_X[ridx[ra] * EE + o] = tanhf(v.x + bf);
        if (rb < cnt) g_X[ridx[rb] * EE + o] = tanhf(v.y + bf);
    }
}

// ---------------------------------------------------------------------------
// Head: out = relu(X @ W1 + b1) @ W2 + b2. Pair-packed f32x2.
// SMEM: float2 SH[16*256] (32KB): phase1 X(p,e)=SH[p*128+e];
// phase2 H(p,h)=SH[p*256+h].
// 512 threads gemm1: oh = tid&255, g = tid>>8 (0..1) -> pairs 8g..8g+7.
// gemm2: row = tid>>4 (0..31), c = tid&15.
// ---------------------------------------------------------------------------
__global__ __launch_bounds__(STHREADS, 1)
void head_kernel(const float* __restrict__ W1, const float* __restrict__ b1,
                 const float* __restrict__ W2, const float* __restrict__ b2,
                 float* __restrict__ out) {
    __shared__ __align__(16) float2 SH[NPAIR * HDIM];   // 32 KB
    int tid  = threadIdx.x;
    int row0 = blockIdx.x * RT;

    float* SHf = (float*)SH;
    for (int i = tid; i < RT * EE; i += STHREADS) {
        int r = i >> 7, e = i & (EE - 1);
        int p = r >> 1, comp = r & 1;
        SHf[p * 256 + 2 * e + comp] = g_X[(row0 + r) * EE + e];
    }
    __syncthreads();

    const int oh = tid & (HDIM - 1);
    const int g  = tid >> 8;        // 0..1
    const int p0 = g * 8;

    ull acc[8];
#pragma unroll
    for (int p = 0; p < 8; p++) acc[p] = 0ull;
#pragma unroll 2
    for (int e = 0; e < EE; e += 2) {
        ull w0 = bcast2(W1[(e + 0) * HDIM + oh]);
        ull w1 = bcast2(W1[(e + 1) * HDIM + oh]);
#pragma unroll
        for (int p = 0; p < 8; p++) {
            int pp = p0 + p;
            ulonglong2 x2 = *(const ulonglong2*)&SH[pp * EE + e];
            acc[p] = fma2(x2.x, w0, acc[p]);
            acc[p] = fma2(x2.y, w1, acc[p]);
        }
    }
    const float bh = b1[oh];
    __syncthreads();
#pragma unroll
    for (int p = 0; p < 8; p++) {
        int pp = p0 + p;
        float2 v = unpack2(acc[p]);
        SH[pp * HDIM + oh] = make_float2(fmaxf(v.x + bh, 0.f), fmaxf(v.y + bh, 0.f));
    }
    __syncthreads();

    // gemm2: each thread one (row, c)
    const int row = tid >> 4;          // 0..31
    const int c   = tid & (CDIM - 1);
    const int pr  = row >> 1, comp = row & 1;
    float sum = b2[c];
#pragma unroll 4
    for (int h = 0; h < HDIM; h += 2) {
        float2 h0 = SH[pr * HDIM + h];
        float2 h1 = SH[pr * HDIM + h + 1];
        float v0 = comp ? h0.y : h0.x;
        float v1 = comp ? h1.y : h1.x;
        sum = fmaf(v0, W2[(h + 0) * CDIM + c], sum);
        sum = fmaf(v1, W2[(h + 1) * CDIM + c], sum);
    }
    out[(row0 + row) * CDIM + c] = sum;
}

// ---------------------------------------------------------------------------
extern "C" void kernel_launch(void* const* d_in, const int* in_sizes, int n_in,
                              void* d_out, int out_size) {
    const int*   entity_ids = (const int*)d_in[0];
    const int*   module_ids = (const int*)d_in[1];
    const float* emb        = (const float*)d_in[2];
    const float* W_in       = (const float*)d_in[3];
    const float* b_in       = (const float*)d_in[4];
    const float* W_bias     = (const float*)d_in[5];
    const float* b_bias     = (const float*)d_in[6];
    const float* W_f        = (const float*)d_in[7];
    const float* b_f        = (const float*)d_in[8];
    const float* W1         = (const float*)d_in[9];
    const float* b1         = (const float*)d_in[10];
    const float* W2         = (const float*)d_in[11];
    const float* b2         = (const float*)d_in[12];
    float* out = (float*)d_out;

    setup_kernel<<<1, 256>>>(module_ids);
    gather_x0<<<(BB * EE) / 256, 256>>>(entity_ids, emb);
    for (int s = 0; s < NSTEPS; s++)
        step_kernel<<<MAX_TILES, STHREADS>>>(s, emb, entity_ids,
                                             W_in, b_in, W_bias, b_bias, W_f, b_f);
    head_kernel<<<BB / RT, STHREADS>>>(W1, b1, W2, b2, out);
}

// round 3
// speedup vs baseline: 1.1771x; 1.0310x over previous
#include <cuda_runtime.h>
#include <math.h>
#include <stdint.h>

#define BB 4096
#define EE 128
#define MMOD 8
#define NSTEPS 3
#define HDIM 256
#define CDIM 16
#define RT 32                 // rows per tile
#define NPAIR (RT/2)          // 16 row-pairs
#define STHREADS 512
#define MAX_TILES (BB/RT + MMOD)   // 136

#define EC1 16                // phase-1 chunk (e rows), 8 chunks
#define NC1 (EE/EC1)
#define EC2 32                // phase-2 chunk (f rows), 8 chunks
#define NC2 (2*EE/EC2)
#define WBUF_FLOATS 4096      // one weight buffer = 16KB
#define DYN_SMEM (8192*4 + 2*WBUF_FLOATS*4)   // 32KB tiles + 32KB arena = 64KB

typedef unsigned long long ull;

// Scratch (static __device__ — no allocation allowed)
__device__ float g_X[BB * EE];                    // recurrent state, 2 MB
__device__ int   g_order[NSTEPS * BB];            // per-step rows sorted by module
__device__ int   g_tiles[NSTEPS * MAX_TILES * 3]; // (module, base, cnt) per tile

// ---------------- f32x2 helpers (FFMA2 path, sm_103a) ----------------------
__device__ __forceinline__ ull bcast2(float v) {
    ull r; asm("mov.b64 %0, {%1, %1};" : "=l"(r) : "f"(v)); return r;
}
__device__ __forceinline__ ull fma2(ull a, ull b, ull c) {
    ull d; asm("fma.rn.f32x2 %0, %1, %2, %3;" : "=l"(d) : "l"(a), "l"(b), "l"(c));
    return d;
}
__device__ __forceinline__ float2 unpack2(ull v) {
    float2 f; asm("mov.b64 {%0, %1}, %2;" : "=f"(f.x), "=f"(f.y) : "l"(v)); return f;
}
// ---------------- cp.async helpers ----------------------------------------
__device__ __forceinline__ uint32_t sptr(const void* p) {
    return (uint32_t)__cvta_generic_to_shared(p);
}
__device__ __forceinline__ void cpa16(uint32_t s, const float* g) {
    asm volatile("cp.async.ca.shared.global [%0], [%1], 16;" :: "r"(s), "l"(g));
}
__device__ __forceinline__ void cpa_commit() {
    asm volatile("cp.async.commit_group;");
}
__device__ __forceinline__ void cpa_wait1() {
    asm volatile("cp.async.wait_group 1;");
}
__device__ __forceinline__ void cpa_wait0() {
    asm volatile("cp.async.wait_group 0;");
}

// ---------------------------------------------------------------------------
// Setup: per-step counting sort of rows by module + tile metadata
// ---------------------------------------------------------------------------
__global__ void setup_kernel(const int* __restrict__ module_ids) {
    __shared__ int cnt[MMOD], cur[MMOD];
    int tid = threadIdx.x;
    for (int s = 0; s < NSTEPS; s++) {
        if (tid < MMOD) cnt[tid] = 0;
        __syncthreads();
        for (int b = tid; b < BB; b += 256)
            atomicAdd(&cnt[module_ids[b * NSTEPS + s]], 1);
        __syncthreads();
        if (tid == 0) {
            int o = 0, t = 0;
            for (int m = 0; m < MMOD; m++) {
                cur[m] = o;
                int c = cnt[m];
                for (int chunk = 0; chunk < c; chunk += RT) {
                    g_tiles[(s * MAX_TILES + t) * 3 + 0] = m;
                    g_tiles[(s * MAX_TILES + t) * 3 + 1] = o + chunk;
                    g_tiles[(s * MAX_TILES + t) * 3 + 2] = min(RT, c - chunk);
                    t++;
                }
                o += c;
            }
            for (; t < MAX_TILES; t++)
                g_tiles[(s * MAX_TILES + t) * 3 + 2] = 0;
        }
        __syncthreads();
        for (int b = tid; b < BB; b += 256) {
            int m = module_ids[b * NSTEPS + s];
            int p = atomicAdd(&cur[m], 1);
            g_order[s * BB + p] = b;
        }
        __syncthreads();
    }
}

// ---------------------------------------------------------------------------
// Gather initial state x0 = embedding[entity_ids[:,0]]
// ---------------------------------------------------------------------------
__global__ void gather_x0(const int* __restrict__ entity_ids,
                          const float* __restrict__ emb) {
    int i = blockIdx.x * blockDim.x + threadIdx.x;  // over BB*EE
    int b = i >> 7, e = i & (EE - 1);
    g_X[i] = emb[(size_t)entity_ids[b * (NSTEPS + 1)] * EE + e];
}

// ---------------------------------------------------------------------------
// One recurrent step for one (module, row-tile). Row-PAIR packed f32x2 math.
// Weights staged into SMEM via double-buffered cp.async (no inner-loop LDG).
// Dynamic SMEM: [0,8192) floats = float2 tiles (X|B then H),
//               [8192,16384) floats = 2x weight buffers (16KB each).
// 512 threads: o = tid&127 (output col), g = tid>>7 (0..3) -> pairs 4g..4g+3.
// ---------------------------------------------------------------------------
__global__ __launch_bounds__(STHREADS, 1)
void step_kernel(int s,
                 const float* __restrict__ emb,
                 const int* __restrict__ entity_ids,
                 const float* __restrict__ W_in,  const float* __restrict__ b_in,
                 const float* __restrict__ W_bias,const float* __restrict__ b_bias,
                 const float* __restrict__ W_f,   const float* __restrict__ b_f) {
    extern __shared__ float dynsm[];
    float2* SH     = (float2*)dynsm;          // 4096 float2
    float*  WARENA = dynsm + 8192;            // 2 x 4096 floats
    __shared__ int ridx[RT];
    __shared__ int eidn[RT];
    __shared__ int s_m, s_base, s_cnt;

    int tid = threadIdx.x;
    if (tid == 0) {
        int t = blockIdx.x;
        s_m    = g_tiles[(s * MAX_TILES + t) * 3 + 0];
        s_base = g_tiles[(s * MAX_TILES + t) * 3 + 1];
        s_cnt  = g_tiles[(s * MAX_TILES + t) * 3 + 2];
    }
    __syncthreads();
    const int cnt = s_cnt;
    if (cnt == 0) return;
    const int m = s_m, base = s_base;

    const float* Wi = W_in   + m * EE * EE;
    const float* Wb = W_bias + m * EE * EE;
    const float* Wf = W_f    + m * 2 * EE * EE;

    // Pre-stage phase-1 chunk 0 immediately (overlaps with the X/B gather)
    {
        uint32_t d = sptr(WARENA) + tid * 16;
        cpa16(d,                 Wi + tid * 4);
        cpa16(d + WBUF_FLOATS*2, Wb + tid * 4);   // offset 2048 floats = 8192B
        cpa_commit();
    }

    if (tid < RT) {
        int row = g_order[s * BB + base + ((tid < cnt) ? tid : 0)];
        ridx[tid] = row;
        eidn[tid] = entity_ids[row * (NSTEPS + 1) + s + 1];
    }
    __syncthreads();

    // Load X tile and Bias tile (gather) into pair-interleaved SMEM
    float* SHf = (float*)SH;
    for (int i = tid; i < RT * EE; i += STHREADS) {
        int r = i >> 7, e = i & (EE - 1);
        int p = r >> 1, comp = r & 1;
        SHf[p * 256 + 2 * e + comp]            = g_X[ridx[r] * EE + e];
        SHf[2 * 2048 + p * 256 + 2 * e + comp] = emb[(size_t)eidn[r] * EE + e];
    }

    const int o = tid & (EE - 1);
    const int g = tid >> 7;          // 0..3
    const int p0 = g * 4;

    ull accI[4], accB[4];
#pragma unroll
    for (int p = 0; p < 4; p++) { accI[p] = 0ull; accB[p] = 0ull; }

    // ------------------- Phase 1: h_in / h_bi (8 chunks of 16 e-rows) ------
    for (int c = 0; c < NC1; c++) {
        if (c + 1 < NC1) {
            float* dst = WARENA + ((c + 1) & 1) * WBUF_FLOATS;
            uint32_t d = sptr(dst) + tid * 16;
            const float* si = Wi + (c + 1) * EC1 * EE;
            const float* sb = Wb + (c + 1) * EC1 * EE;
            cpa16(d,        si + tid * 4);
            cpa16(d + 8192, sb + tid * 4);
            cpa_commit();
            cpa_wait1();
        } else {
            cpa_wait0();
        }
        __syncthreads();
        const float* WB = WARENA + (c & 1) * WBUF_FLOATS;
        const int e0 = c * EC1;
#pragma unroll
        for (int e = 0; e < EC1; e += 2) {
            ull wi0 = bcast2(WB[(e + 0) * EE + o]);
            ull wi1 = bcast2(WB[(e + 1) * EE + o]);
            ull wb0 = bcast2(WB[2048 + (e + 0) * EE + o]);
            ull wb1 = bcast2(WB[2048 + (e + 1) * EE + o]);
            int ge = e0 + e;
#pragma unroll
            for (int p = 0; p < 4; p++) {
                int pp = p0 + p;
                ulonglong2 x2 = *(const ulonglong2*)&SH[pp * EE + ge];
                accI[p] = fma2(x2.x, wi0, accI[p]);
                accI[p] = fma2(x2.y, wi1, accI[p]);
                ulonglong2 b2 = *(const ulonglong2*)&SH[2048 + pp * EE + ge];
                accB[p] = fma2(b2.x, wb0, accB[p]);
                accB[p] = fma2(b2.y, wb1, accB[p]);
            }
        }
        __syncthreads();
    }

    // Pre-stage phase-2 chunk 0 (overlaps with H writeback)
    {
        float* dst = WARENA;                       // buf0 (free: last p1 chunk used buf1)
        uint32_t d = sptr(dst) + tid * 16;
        const float* sf = Wf;                      // f-rows 0..31 = 4096 floats
        cpa16(d,        sf + tid * 4);
        cpa16(d + 8192, sf + 2048 + tid * 4);
        cpa_commit();
    }

    const float bi = b_in[m * EE + o];
    const float bb = b_bias[m * EE + o];
#pragma unroll
    for (int p = 0; p < 4; p++) {
        int pp = p0 + p;
        float2 vI = unpack2(accI[p]);
        float2 vB = unpack2(accB[p]);
        SH[pp * 256 + o]      = make_float2(fmaxf(vI.x + bi, 0.f), fmaxf(vI.y + bi, 0.f));
        SH[pp * 256 + EE + o] = make_float2(fmaxf(vB.x + bb, 0.f), fmaxf(vB.y + bb, 0.f));
    }

    // ------------------- Phase 2: x' = tanh(H @ W_f + b_f) -----------------
    ull accF[4];
#pragma unroll
    for (int p = 0; p < 4; p++) accF[p] = 0ull;

    for (int c = 0; c < NC2; c++) {
        if (c + 1 < NC2) {
            float* dst = WARENA + ((c + 1) & 1) * WBUF_FLOATS;
            uint32_t d = sptr(dst) + tid * 16;
            const float* sf = Wf + (c + 1) * EC2 * EE;
            cpa16(d,        sf + tid * 4);
            cpa16(d + 8192, sf + 2048 + tid * 4);
            cpa_commit();
            cpa_wait1();
        } else {
            cpa_wait0();
        }
        __syncthreads();
        const float* WB = WARENA + (c & 1) * WBUF_FLOATS;
        const int f0 = c * EC2;
#pragma unroll
        for (int f = 0; f < EC2; f += 2) {
            ull w0 = bcast2(WB[(f + 0) * EE + o]);
            ull w1 = bcast2(WB[(f + 1) * EE + o]);
            int gf = f0 + f;
#pragma unroll
            for (int p = 0; p < 4; p++) {
                int pp = p0 + p;
                ulonglong2 h2 = *(const ulonglong2*)&SH[pp * 256 + gf];
                accF[p] = fma2(h2.x, w0, accF[p]);
                accF[p] = fma2(h2.y, w1, accF[p]);
            }
        }
        __syncthreads();
    }

    const float bf = b_f[m * EE + o];
#pragma unroll
    for (int p = 0; p < 4; p++) {
        int pp = p0 + p;
        float2 v = unpack2(accF[p]);
        int ra = 2 * pp, rb = 2 * pp + 1;
        if (ra < cnt) g_X[ridx[ra] * EE + o] = tanhf(v.x + bf);
        if (rb < cnt) g_X[ridx[rb] * EE + o] = tanhf(v.y + bf);
    }
}

// ---------------------------------------------------------------------------
// Head: out = relu(X @ W1 + b1) @ W2 + b2. Pair-packed f32x2, staged weights.
// ---------------------------------------------------------------------------
__global__ __launch_bounds__(STHREADS, 1)
void head_kernel(const float* __restrict__ W1, const float* __restrict__ b1,
                 const float* __restrict__ W2, const float* __restrict__ b2,
                 float* __restrict__ out) {
    extern __shared__ float dynsm[];
    float2* SH     = (float2*)dynsm;          // 4096 float2 (X then H)
    float*  WARENA = dynsm + 8192;
    int tid  = threadIdx.x;
    int row0 = blockIdx.x * RT;

    // Pre-stage W1 chunk 0 (16 e-rows x 256 = 4096 floats)
    {
        uint32_t d = sptr(WARENA) + tid * 16;
        cpa16(d,        W1 + tid * 4);
        cpa16(d + 8192, W1 + 2048 + tid * 4);
        cpa_commit();
    }

    float* SHf = (float*)SH;
    for (int i = tid; i < RT * EE; i += STHREADS) {
        int r = i >> 7, e = i & (EE - 1);
        int p = r >> 1, comp = r & 1;
        SHf[p * 256 + 2 * e + comp] = g_X[(row0 + r) * EE + e];
    }

    const int oh = tid & (HDIM - 1);
    const int g  = tid >> 8;        // 0..1
    const int p0 = g * 8;

    ull acc[8];
#pragma unroll
    for (int p = 0; p < 8; p++) acc[p] = 0ull;

    const int HC = 16, NHC = EE / HC;   // 8 chunks of 16 e-rows
    for (int c = 0; c < NHC; c++) {
        if (c + 1 < NHC) {
            float* dst = WARENA + ((c + 1) & 1) * WBUF_FLOATS;
            uint32_t d = sptr(dst) + tid * 16;
            const float* s1 = W1 + (c + 1) * HC * HDIM;
            cpa16(d,        s1 + tid * 4);
            cpa16(d + 8192, s1 + 2048 + tid * 4);
            cpa_commit();
            cpa_wait1();
        } else {
            cpa_wait0();
        }
        __syncthreads();
        const float* WB = WARENA + (c & 1) * WBUF_FLOATS;
        const int e0 = c * HC;
#pragma unroll
        for (int e = 0; e < HC; e += 2) {
            ull w0 = bcast2(WB[(e + 0) * HDIM + oh]);
            ull w1 = bcast2(WB[(e + 1) * HDIM + oh]);
            int ge = e0 + e;
#pragma unroll
            for (int p = 0; p < 8; p++) {
                int pp = p0 + p;
                ulonglong2 x2 = *(const ulonglong2*)&SH[pp * EE + ge];
                acc[p] = fma2(x2.x, w0, acc[p]);
                acc[p] = fma2(x2.y, w1, acc[p]);
            }
        }
        __syncthreads();
    }

    // Stage W2 (256x16 = 4096 floats) into buf0 while writing H
    {
        uint32_t d = sptr(WARENA) + tid * 16;
        cpa16(d,        W2 + tid * 4);
        cpa16(d + 8192, W2 + 2048 + tid * 4);
        cpa_commit();
    }

    const float bh = b1[oh];
#pragma unroll
    for (int p = 0; p < 8; p++) {
        int pp = p0 + p;
        float2 v = unpack2(acc[p]);
        SH[pp * HDIM + oh] = make_float2(fmaxf(v.x + bh, 0.f), fmaxf(v.y + bh, 0.f));
    }
    cpa_wait0();
    __syncthreads();

    // gemm2: each thread one (row, c)
    const float* WB2 = WARENA;
    const int row = tid >> 4;          // 0..31
    const int c   = tid & (CDIM - 1);
    const int pr  = row >> 1, comp = row & 1;
    float sum = b2[c];
#pragma unroll 4
    for (int h = 0; h < HDIM; h += 2) {
        float2 h0 = SH[pr * HDIM + h];
        float2 h1 = SH[pr * HDIM + h + 1];
        float v0 = comp ? h0.y : h0.x;
        float v1 = comp ? h1.y : h1.x;
        sum = fmaf(v0, WB2[(h + 0) * CDIM + c], sum);
        sum = fmaf(v1, WB2[(h + 1) * CDIM + c], sum);
    }
    out[(row0 + row) * CDIM + c] = sum;
}

// ---------------------------------------------------------------------------
extern "C" void kernel_launch(void* const* d_in, const int* in_sizes, int n_in,
                              void* d_out, int out_size) {
    const int*   entity_ids = (const int*)d_in[0];
    const int*   module_ids = (const int*)d_in[1];
    const float* emb        = (const float*)d_in[2];
    const float* W_in       = (const float*)d_in[3];
    const float* b_in       = (const float*)d_in[4];
    const float* W_bias     = (const float*)d_in[5];
    const float* b_bias     = (const float*)d_in[6];
    const float* W_f        = (const float*)d_in[7];
    const float* b_f        = (const float*)d_in[8];
    const float* W1         = (const float*)d_in[9];
    const float* b1         = (const float*)d_in[10];
    const float* W2         = (const float*)d_in[11];
    const float* b2         = (const float*)d_in[12];
    float* out = (float*)d_out;

    cudaFuncSetAttribute(step_kernel, cudaFuncAttributeMaxDynamicSharedMemorySize, DYN_SMEM);
    cudaFuncSetAttribute(head_kernel, cudaFuncAttributeMaxDynamicSharedMemorySize, DYN_SMEM);

    setup_kernel<<<1, 256>>>(module_ids);
    gather_x0<<<(BB * EE) / 256, 256>>>(entity_ids, emb);
    for (int s = 0; s < NSTEPS; s++)
        step_kernel<<<MAX_TILES, STHREADS, DYN_SMEM>>>(s, emb, entity_ids,
                                                       W_in, b_in, W_bias, b_bias, W_f, b_f);
    head_kernel<<<BB / RT, STHREADS, DYN_SMEM>>>(W1, b1, W2, b2, out);
}